// round 2
// baseline (speedup 1.0000x reference)
#include <cuda_runtime.h>

// FractalEmbedding: out[b,l,d] = scale * sum_f julia_feats(token[b,l])[f] * W[d,f]
// B*L = 65536 tokens, EMBED_DIM = 1024, F = 16 (8 Julia steps x {zr,zi}).
//
// R2: occupancy-bound fix. 2 dims/thread (32 W regs instead of 64), gridDim.y=2
// dim-halves, __launch_bounds__(256,4) -> target 32 warps/SM (was 16). Packed
// fma.rn.f32x2 matvec, STG.64 coalesced stores.

#define THREADS 256
#define T_TOK   64

__device__ __forceinline__ unsigned long long pk2(float lo, float hi) {
    unsigned long long r;
    asm("mov.b64 %0, {%1, %2};" : "=l"(r) : "f"(lo), "f"(hi));
    return r;
}
__device__ __forceinline__ void upk2(float& lo, float& hi, unsigned long long v) {
    asm("mov.b64 {%0, %1}, %2;" : "=f"(lo), "=f"(hi) : "l"(v));
}
__device__ __forceinline__ unsigned long long mul2(unsigned long long a, unsigned long long b) {
    unsigned long long r;
    asm("mul.rn.f32x2 %0, %1, %2;" : "=l"(r) : "l"(a), "l"(b));
    return r;
}
__device__ __forceinline__ void fma2(unsigned long long& d, unsigned long long a, unsigned long long b) {
    asm("fma.rn.f32x2 %0, %1, %2, %0;" : "+l"(d) : "l"(a), "l"(b));
}

__global__ __launch_bounds__(THREADS, 4)
void fractal_embed_kernel(const int* __restrict__ tok,
                          const float2* __restrict__ ctab,
                          const float4* __restrict__ Wv,
                          const float* __restrict__ scale_p,
                          float2* __restrict__ out)
{
    __shared__ float sfeat[T_TOK][16];   // per-token features, scale pre-folded

    const int tid  = threadIdx.x;
    const int base = blockIdx.x * T_TOK;

    // --- Register-resident W slice: 2 rows (dims d0, d0+1) x 16 f, packed f32x2 ---
    const int d0 = blockIdx.y * 512 + tid * 2;
    unsigned long long wp[2][8];
#pragma unroll
    for (int j = 0; j < 2; ++j) {
        const float4* row = Wv + (size_t)(d0 + j) * 4;   // 16 floats = 4 float4
#pragma unroll
        for (int q = 0; q < 4; ++q) {
            float4 v = row[q];
            wp[j][2 * q]     = pk2(v.x, v.y);
            wp[j][2 * q + 1] = pk2(v.z, v.w);
        }
    }

    const float s = *scale_p;

    // --- Phase 1: threads 0..63 compute Julia features for this tile's tokens ---
    if (tid < T_TOK) {
        int t = tok[base + tid];
        float2 c = ctab[t];
        float zr = 0.f, zi = 0.f;
#pragma unroll
        for (int k = 0; k < 8; ++k) {
            float nr = zr * zr - zi * zi + c.x;
            float ni = 2.f * zr * zi + c.y;
            zr = nr; zi = ni;
            sfeat[tid][2 * k]     = zr * s;
            sfeat[tid][2 * k + 1] = zi * s;
        }
    }
    __syncthreads();

    // --- Phase 2: matvec per token; broadcast LDS.64 feats, packed FMAs, STG.64 ---
    float2* obase = out + (size_t)base * 512 + (size_t)blockIdx.y * 256 + tid;
    for (int i = 0; i < T_TOK; ++i) {
        const float2* fp = reinterpret_cast<const float2*>(sfeat[i]);
        unsigned long long a0, a1;
        {
            float2 fv = fp[0];
            unsigned long long sp = pk2(fv.x, fv.y);
            a0 = mul2(sp, wp[0][0]);
            a1 = mul2(sp, wp[1][0]);
        }
#pragma unroll
        for (int p = 1; p < 8; ++p) {
            float2 fv = fp[p];
            unsigned long long sp = pk2(fv.x, fv.y);
            fma2(a0, sp, wp[0][p]);
            fma2(a1, sp, wp[1][p]);
        }
        float lo, hi;
        float2 o;
        upk2(lo, hi, a0); o.x = lo + hi;
        upk2(lo, hi, a1); o.y = lo + hi;
        obase[(size_t)i * 512] = o;   // token i, dims [d0, d0+1]
    }
}

extern "C" void kernel_launch(void* const* d_in, const int* in_sizes, int n_in,
                              void* d_out, int out_size)
{
    const int*    tok  = (const int*)d_in[0];      // token_ids (B*L,) int32
    const float2* ctab = (const float2*)d_in[1];   // c_table (V, 2) f32
    const float4* Wv   = (const float4*)d_in[2];   // W (1024, 16) f32 row-major
    const float*  scl  = (const float*)d_in[3];    // scale scalar f32
    float2* out = (float2*)d_out;                  // (B, L, 1024) f32 as float2

    int n_tok = in_sizes[0];                 // 65536
    dim3 grid(n_tok / T_TOK, 2);             // 1024 token tiles x 2 dim-halves
    fractal_embed_kernel<<<grid, THREADS>>>(tok, ctab, Wv, scl, out);
}

// round 5
// speedup vs baseline: 1.1399x; 1.1399x over previous
#include <cuda_runtime.h>

// FractalEmbedding: out[b,l,d] = scale * sum_f julia_feats(token[b,l])[f] * W[d,f]
// B*L = 65536 tokens, EMBED_DIM = 1024, F = 16 (8 Julia steps x {zr,zi}).
//
// R3: R1 shape (4 dims/thread, STG.128) minus issue-slot waste:
//  - features stored in smem as u64 pairs, loaded via LDS.128 (no pk2 movs,
//    half the feature-LDS count)
//  - token loop unrolled x4 (immediate store offsets, cross-token ILP)
//  - streaming stores

#define THREADS 256
#define T_TOK   64

__device__ __forceinline__ unsigned long long pk2(float lo, float hi) {
    unsigned long long r;
    asm("mov.b64 %0, {%1, %2};" : "=l"(r) : "f"(lo), "f"(hi));
    return r;
}
__device__ __forceinline__ void upk2(float& lo, float& hi, unsigned long long v) {
    asm("mov.b64 {%0, %1}, %2;" : "=f"(lo), "=f"(hi) : "l"(v));
}
__device__ __forceinline__ unsigned long long mul2(unsigned long long a, unsigned long long b) {
    unsigned long long r;
    asm("mul.rn.f32x2 %0, %1, %2;" : "=l"(r) : "l"(a), "l"(b));
    return r;
}
__device__ __forceinline__ void fma2(unsigned long long& d, unsigned long long a, unsigned long long b) {
    asm("fma.rn.f32x2 %0, %1, %2, %0;" : "+l"(d) : "l"(a), "l"(b));
}

__global__ __launch_bounds__(THREADS, 2)
void fractal_embed_kernel(const int* __restrict__ tok,
                          const float2* __restrict__ ctab,
                          const float4* __restrict__ Wv,
                          const float* __restrict__ scale_p,
                          float4* __restrict__ out)
{
    // Features as packed u64 pairs: sfeat[i][p] = (feat[2p], feat[2p+1]); 64B rows.
    __shared__ unsigned long long sfeat[T_TOK][8];

    const int tid  = threadIdx.x;
    const int base = blockIdx.x * T_TOK;

    // --- Register-resident W slice: 4 rows (dims d0..d0+3) x 16 f, packed f32x2 ---
    const int d0 = tid * 4;
    unsigned long long wp[4][8];
#pragma unroll
    for (int j = 0; j < 4; ++j) {
        const float4* row = Wv + (size_t)(d0 + j) * 4;   // 16 floats = 4 float4
#pragma unroll
        for (int q = 0; q < 4; ++q) {
            float4 v = row[q];
            wp[j][2 * q]     = pk2(v.x, v.y);
            wp[j][2 * q + 1] = pk2(v.z, v.w);
        }
    }

    const float s = *scale_p;

    // --- Phase 1: threads 0..63 compute Julia features (scale folded in) ---
    if (tid < T_TOK) {
        int t = tok[base + tid];
        float2 c = ctab[t];
        float zr = 0.f, zi = 0.f;
        float* frow = reinterpret_cast<float*>(sfeat[tid]);
#pragma unroll
        for (int k = 0; k < 8; ++k) {
            float nr = zr * zr - zi * zi + c.x;
            float ni = 2.f * zr * zi + c.y;
            zr = nr; zi = ni;
            frow[2 * k]     = zr * s;
            frow[2 * k + 1] = zi * s;
        }
    }
    __syncthreads();

    // --- Phase 2: per token: 4x LDS.128 feats, 32 packed FMAs, 1x STG.128 ---
    float4* obase = out + (size_t)base * 256 + tid;
#pragma unroll 4
    for (int i = 0; i < T_TOK; ++i) {
        const ulonglong2* fp = reinterpret_cast<const ulonglong2*>(sfeat[i]);
        ulonglong2 fA = fp[0];   // feats 0..3  packed as two f32x2
        ulonglong2 fB = fp[1];   // feats 4..7
        ulonglong2 fC = fp[2];   // feats 8..11
        ulonglong2 fD = fp[3];   // feats 12..15

        unsigned long long a0 = mul2(fA.x, wp[0][0]);
        unsigned long long a1 = mul2(fA.x, wp[1][0]);
        unsigned long long a2 = mul2(fA.x, wp[2][0]);
        unsigned long long a3 = mul2(fA.x, wp[3][0]);

        fma2(a0, fA.y, wp[0][1]); fma2(a1, fA.y, wp[1][1]);
        fma2(a2, fA.y, wp[2][1]); fma2(a3, fA.y, wp[3][1]);

        fma2(a0, fB.x, wp[0][2]); fma2(a1, fB.x, wp[1][2]);
        fma2(a2, fB.x, wp[2][2]); fma2(a3, fB.x, wp[3][2]);

        fma2(a0, fB.y, wp[0][3]); fma2(a1, fB.y, wp[1][3]);
        fma2(a2, fB.y, wp[2][3]); fma2(a3, fB.y, wp[3][3]);

        fma2(a0, fC.x, wp[0][4]); fma2(a1, fC.x, wp[1][4]);
        fma2(a2, fC.x, wp[2][4]); fma2(a3, fC.x, wp[3][4]);

        fma2(a0, fC.y, wp[0][5]); fma2(a1, fC.y, wp[1][5]);
        fma2(a2, fC.y, wp[2][5]); fma2(a3, fC.y, wp[3][5]);

        fma2(a0, fD.x, wp[0][6]); fma2(a1, fD.x, wp[1][6]);
        fma2(a2, fD.x, wp[2][6]); fma2(a3, fD.x, wp[3][6]);

        fma2(a0, fD.y, wp[0][7]); fma2(a1, fD.y, wp[1][7]);
        fma2(a2, fD.y, wp[2][7]); fma2(a3, fD.y, wp[3][7]);

        float4 o;
        float lo, hi;
        upk2(lo, hi, a0); o.x = lo + hi;
        upk2(lo, hi, a1); o.y = lo + hi;
        upk2(lo, hi, a2); o.z = lo + hi;
        upk2(lo, hi, a3); o.w = lo + hi;
        __stcs(obase + (size_t)i * 256, o);   // streaming STG.128
    }
}

extern "C" void kernel_launch(void* const* d_in, const int* in_sizes, int n_in,
                              void* d_out, int out_size)
{
    const int*    tok  = (const int*)d_in[0];      // token_ids (B*L,) int32
    const float2* ctab = (const float2*)d_in[1];   // c_table (V, 2) f32
    const float4* Wv   = (const float4*)d_in[2];   // W (1024, 16) f32 row-major
    const float*  scl  = (const float*)d_in[3];    // scale scalar f32
    float4* out = (float4*)d_out;                  // (B, L, 1024) f32

    int n_tok  = in_sizes[0];        // 65536
    int blocks = n_tok / T_TOK;      // 1024
    fractal_embed_kernel<<<blocks, THREADS>>>(tok, ctab, Wv, scl, out);
}